// round 16
// baseline (speedup 1.0000x reference)
#include <cuda_runtime.h>
#include <cuda_bf16.h>
#include <cstdint>
#include <math.h>

#define NNODES 100000
#define NEDGES 1600000
#define SCAN_BS 256
#define BKP 40
#define ARR (128 * BKP)
#define GEMM_SMEM (2 * 4 * ARR * 2)   // 81920 B
#define NCHUNK 4

// ---------------------------------------------------------------------------
// Scratch (device globals)
// ---------------------------------------------------------------------------
__device__ float g_dis[NNODES];
__device__ __nv_bfloat16 g_pDhi[(size_t)NNODES * 128], g_pDlo[(size_t)NNODES * 128];
__device__ __nv_bfloat16 g_pAhi[(size_t)NNODES * 256], g_pAlo[(size_t)NNODES * 256];
__device__ float g_z[(size_t)NNODES * 16];
__device__ float g_y[(size_t)NNODES * 2];
__device__ float g_y2[(size_t)NNODES * 2];
__device__ int   g_cnt[NNODES];
__device__ int   g_cur[NNODES];
__device__ int   g_rowptr[NNODES + 1];
__device__ int   g_btot[(NNODES + SCAN_BS - 1) / SCAN_BS + 1];
__device__ int   g_boff[(NNODES + SCAN_BS - 1) / SCAN_BS + 1];
__device__ int   g_csr_src[NEDGES];
__device__ float g_csr_norm[NEDGES];
__device__ int   g_is64;
__device__ __nv_bfloat16 g_whi[32768], g_wlo[32768];       // W1 [n][k] split
__device__ __nv_bfloat16 g_Ghi[4096], g_Glo[4096];          // G=W2Wc [j][k] split
__device__ float g_c0[16];
__device__ float g_q[256];
__device__ float g_s[4][2];

// ---------------------------------------------------------------------------
// Preprocessing
// ---------------------------------------------------------------------------
__global__ void init_kernel(const void* ei_raw, int N) {
    int i = blockIdx.x * blockDim.x + threadIdx.x;
    if (i < N) { g_cnt[i] = 0; g_cur[i] = 0; }
    if (i == 0) {
        const long long* p = (const long long*)ei_raw;
        int ok = 1;
        for (int k = 0; k < 8; k++) {
            long long v = p[k];
            if (v < 0 || v >= (long long)N) ok = 0;
        }
        g_is64 = ok;
    }
}

__global__ void count_kernel(const void* ei_raw, int E) {
    int e = blockIdx.x * blockDim.x + threadIdx.x;
    if (e >= E) return;
    int c;
    if (g_is64) {
        const long long* p = (const long long*)ei_raw;
        c = (int)p[(size_t)E + e];
    } else {
        const int* p = (const int*)ei_raw;
        c = p[E + e];
    }
    atomicAdd(&g_cnt[c], 1);
}

__global__ void scan_blocks_kernel(int N) {
    __shared__ int s[SCAN_BS];
    int i = blockIdx.x * SCAN_BS + threadIdx.x;
    int v = (i < N) ? g_cnt[i] : 0;
    s[threadIdx.x] = v;
    __syncthreads();
    for (int off = 1; off < SCAN_BS; off <<= 1) {
        int t = (threadIdx.x >= off) ? s[threadIdx.x - off] : 0;
        __syncthreads();
        s[threadIdx.x] += t;
        __syncthreads();
    }
    if (i < N) g_rowptr[i] = s[threadIdx.x] - v;
    if (threadIdx.x == SCAN_BS - 1) g_btot[blockIdx.x] = s[SCAN_BS - 1];
}

__global__ void scan_tops_kernel(int nblocks) {
    __shared__ int s[512];
    int v = (threadIdx.x < nblocks) ? g_btot[threadIdx.x] : 0;
    s[threadIdx.x] = v;
    __syncthreads();
    for (int off = 1; off < 512; off <<= 1) {
        int t = (threadIdx.x >= off) ? s[threadIdx.x - off] : 0;
        __syncthreads();
        s[threadIdx.x] += t;
        __syncthreads();
    }
    if (threadIdx.x < nblocks) g_boff[threadIdx.x] = s[threadIdx.x] - v;
}

__global__ void scan_add_fin_kernel(int N, int E) {
    int i = blockIdx.x * SCAN_BS + threadIdx.x;
    if (i < N) {
        g_rowptr[i] += g_boff[blockIdx.x];
        g_dis[i] = rsqrtf((float)g_cnt[i] + 1.0f);
    }
    if (i == 0) g_rowptr[N] = E;
}

__global__ void fill_csr_kernel(const void* ei_raw, int E) {
    int e = blockIdx.x * blockDim.x + threadIdx.x;
    if (e >= E) return;
    int r, c;
    if (g_is64) {
        const long long* p = (const long long*)ei_raw;
        r = (int)p[e];
        c = (int)p[(size_t)E + e];
    } else {
        const int* p = (const int*)ei_raw;
        r = p[e];
        c = p[E + e];
    }
    int pos = g_rowptr[c] + atomicAdd(&g_cur[c], 1);
    g_csr_src[pos] = r;
    g_csr_norm[pos] = g_dis[r] * g_dis[c];
}

// W1 [K=128][F=256] fp32 -> whi/wlo [F][K] bf16
__global__ void conv_w_kernel(const float* __restrict__ W) {
    int idx = blockIdx.x * blockDim.x + threadIdx.x;
    if (idx >= 128 * 256) return;
    int k = idx / 256;
    int n = idx % 256;
    float wv = W[idx];
    __nv_bfloat16 h = __float2bfloat16(wv);
    g_whi[n * 128 + k] = h;
    g_wlo[n * 128 + k] = __float2bfloat16(wv - __bfloat162float(h));
}

// G = W2 @ Wc (256x16) -> split [j][k]; c0 = b2ᵀWc + bc
__global__ void gwc_kernel(const float* __restrict__ W2, const float* __restrict__ Wc,
                           const float* __restrict__ b2, const float* __restrict__ bc) {
    int j = blockIdx.x;
    int m = threadIdx.x;
    float s = 0.f;
    for (int k = 0; k < 128; k++) s += W2[m * 128 + k] * Wc[k * 16 + j];
    __nv_bfloat16 h = __float2bfloat16(s);
    g_Ghi[j * 256 + m] = h;
    g_Glo[j * 256 + m] = __float2bfloat16(s - __bfloat162float(h));
    if (m == 0) {
        float c = 0.f;
        for (int k = 0; k < 128; k++) c += b2[k] * Wc[k * 16 + j];
        g_c0[j] = c + bc[j];
    }
}

// Encoder weight chain
__global__ void enc_chain_kernel(const float* We1, const float* We2, const float* We3,
                                 const float* We4, const float* Wt,
                                 const float* be1, const float* be2, const float* be3,
                                 const float* be4, const float* bt) {
    __shared__ float a[256], b[256];
    int tid = threadIdx.x;
    int row = tid >> 1, j = tid & 1;
    float s;

    s = 0.f;
    for (int k = 0; k < 128; k++) s += We4[row * 128 + k] * Wt[k * 2 + j];
    a[tid] = s;
    __syncthreads();

    if (tid < 2) {
        float acc = 0.f;
        for (int k = 0; k < 128; k++) acc += be3[k] * a[k * 2 + tid];
        g_s[2][tid] = acc;
        float a4 = 0.f;
        for (int k = 0; k < 128; k++) a4 += be4[k] * Wt[k * 2 + tid];
        g_s[3][tid] = a4 + bt[tid];
    }
    s = 0.f;
    for (int k = 0; k < 128; k++) s += We3[row * 128 + k] * a[k * 2 + j];
    b[tid] = s;
    __syncthreads();

    if (tid < 2) {
        float acc = 0.f;
        for (int k = 0; k < 128; k++) acc += be2[k] * b[k * 2 + tid];
        g_s[1][tid] = acc;
    }
    s = 0.f;
    for (int k = 0; k < 128; k++) s += We2[row * 128 + k] * b[k * 2 + j];
    __syncthreads();
    a[tid] = s;
    __syncthreads();

    if (tid < 2) {
        float acc = 0.f;
        for (int k = 0; k < 128; k++) acc += be1[k] * a[k * 2 + tid];
        g_s[0][tid] = acc;
    }
    s = 0.f;
    for (int k = 0; k < 128; k++) s += We1[row * 128 + k] * a[k * 2 + j];
    g_q[tid] = s;
}

// ---------------------------------------------------------------------------
// PTX helpers
// ---------------------------------------------------------------------------
__device__ __forceinline__ void mma16816(float* d, const uint32_t* a, const uint32_t* b) {
    asm volatile("mma.sync.aligned.m16n8k16.row.col.f32.bf16.bf16.f32 "
        "{%0,%1,%2,%3}, {%4,%5,%6,%7}, {%8,%9}, {%0,%1,%2,%3};"
        : "+f"(d[0]), "+f"(d[1]), "+f"(d[2]), "+f"(d[3])
        : "r"(a[0]), "r"(a[1]), "r"(a[2]), "r"(a[3]), "r"(b[0]), "r"(b[1]));
}
__device__ __forceinline__ void ldsm4(uint32_t* r, uint32_t addr) {
    asm volatile("ldmatrix.sync.aligned.m8n8.x4.shared.b16 {%0,%1,%2,%3}, [%4];"
        : "=r"(r[0]), "=r"(r[1]), "=r"(r[2]), "=r"(r[3]) : "r"(addr));
}
__device__ __forceinline__ void cpa16(uint32_t dst, const __nv_bfloat16* src, int bytes) {
    asm volatile("cp.async.cg.shared.global [%0], [%1], 16, %2;"
                 :: "r"(dst), "l"(src), "r"(bytes));
}

// ---------------------------------------------------------------------------
// Main GEMM (rows [m0off + blockIdx.x*128, ...)), O = split(relu(D + bias))
// ---------------------------------------------------------------------------
__global__ __launch_bounds__(256, 2)
void mma_gemm_kernel(const __nv_bfloat16* __restrict__ Ahi_g,
                     const __nv_bfloat16* __restrict__ Alo_g,
                     const __nv_bfloat16* __restrict__ whi,
                     const __nv_bfloat16* __restrict__ wlo,
                     const float* __restrict__ bias,
                     __nv_bfloat16* __restrict__ Ohi, __nv_bfloat16* __restrict__ Olo,
                     int m0off, int N, int K, int F)
{
    extern __shared__ __nv_bfloat16 sm[];
    const uint32_t smBase = (uint32_t)__cvta_generic_to_shared(sm);

    const int tid = threadIdx.x;
    const int lane = tid & 31;
    const int w = tid >> 5;
    const int wm = w >> 1;
    const int wn = w & 1;
    const int m0 = m0off + blockIdx.x * 128;
    const int n0 = blockIdx.y * 128;

    const int crow = tid >> 1;
    const int cseg = (tid & 1) * 16;
    const int arow = m0 + crow;
    const int aval = (arow < N) ? 16 : 0;
    const int arowc = (arow < N) ? arow : 0;
    const __nv_bfloat16* aHi = Ahi_g + (size_t)arowc * K;
    const __nv_bfloat16* aLo = Alo_g + (size_t)arowc * K;
    const __nv_bfloat16* bHi = whi + (size_t)(n0 + crow) * K;
    const __nv_bfloat16* bLo = wlo + (size_t)(n0 + crow) * K;

#define LOAD_STAGE(st, k0) do {                                                  \
    uint32_t b_ = smBase + (uint32_t)(st) * (4 * ARR * 2);                       \
    uint32_t dA = b_ + (uint32_t)(crow * BKP + cseg) * 2;                        \
    cpa16(dA,                aHi + (k0) + cseg,     aval);                       \
    cpa16(dA + 16,           aHi + (k0) + cseg + 8, aval);                       \
    cpa16(dA + ARR * 2,      aLo + (k0) + cseg,     aval);                       \
    cpa16(dA + ARR * 2 + 16, aLo + (k0) + cseg + 8, aval);                       \
    cpa16(dA + 2 * ARR * 2,      bHi + (k0) + cseg,     16);                     \
    cpa16(dA + 2 * ARR * 2 + 16, bHi + (k0) + cseg + 8, 16);                     \
    cpa16(dA + 3 * ARR * 2,      bLo + (k0) + cseg,     16);                     \
    cpa16(dA + 3 * ARR * 2 + 16, bLo + (k0) + cseg + 8, 16);                     \
    asm volatile("cp.async.commit_group;");                                      \
} while (0)

    const int t  = lane >> 3;
    const int tr = lane & 7;
    const int a_row_l = wm * 32 + (t & 1) * 8 + tr;
    const int a_koff  = (t >> 1) * 8;
    const int b_row_l = wn * 64 + (t >> 1) * 8 + tr;
    const int b_koff  = (t & 1) * 8;

    float acc[2][8][4];
#pragma unroll
    for (int mi = 0; mi < 2; mi++)
#pragma unroll
        for (int nf = 0; nf < 8; nf++)
#pragma unroll
            for (int c = 0; c < 4; c++) acc[mi][nf][c] = 0.f;

    const int nch = K >> 5;
    LOAD_STAGE(0, 0);

    for (int ch = 0; ch < nch; ch++) {
        if (ch + 1 < nch) {
            LOAD_STAGE((ch + 1) & 1, (ch + 1) << 5);
            asm volatile("cp.async.wait_group 1;");
        } else {
            asm volatile("cp.async.wait_group 0;");
        }
        __syncthreads();

        const uint32_t sb = smBase + (uint32_t)(ch & 1) * (4 * ARR * 2);
        const uint32_t aAhi = sb;
        const uint32_t aAlo = sb + ARR * 2;
        const uint32_t aBhi = sb + 2 * ARR * 2;
        const uint32_t aBlo = sb + 3 * ARR * 2;

#pragma unroll
        for (int s = 0; s < 2; s++) {
            const int kb = s * 16;
            uint32_t ahi[2][4], alo[2][4];
#pragma unroll
            for (int mi = 0; mi < 2; mi++) {
                uint32_t off = (uint32_t)(((a_row_l + mi * 16) * BKP + kb + a_koff) * 2);
                ldsm4(ahi[mi], aAhi + off);
                ldsm4(alo[mi], aAlo + off);
            }
            uint32_t bhi[8][2], blo[8][2];
#pragma unroll
            for (int q = 0; q < 4; q++) {
                uint32_t off = (uint32_t)(((b_row_l + q * 16) * BKP + kb + b_koff) * 2);
                uint32_t r4[4];
                ldsm4(r4, aBhi + off);
                bhi[2 * q][0] = r4[0]; bhi[2 * q][1] = r4[1];
                bhi[2 * q + 1][0] = r4[2]; bhi[2 * q + 1][1] = r4[3];
                ldsm4(r4, aBlo + off);
                blo[2 * q][0] = r4[0]; blo[2 * q][1] = r4[1];
                blo[2 * q + 1][0] = r4[2]; blo[2 * q + 1][1] = r4[3];
            }
#pragma unroll
            for (int mi = 0; mi < 2; mi++)
#pragma unroll
                for (int nf = 0; nf < 8; nf++) {
                    mma16816(acc[mi][nf], ahi[mi], bhi[nf]);
                    mma16816(acc[mi][nf], ahi[mi], blo[nf]);
                    mma16816(acc[mi][nf], alo[mi], bhi[nf]);
                }
        }
        __syncthreads();
    }
#undef LOAD_STAGE

    const int crow0 = m0 + wm * 32 + (lane >> 2);
    const int ccol0 = n0 + wn * 64 + (lane & 3) * 2;
#pragma unroll
    for (int mi = 0; mi < 2; mi++) {
        int r1 = crow0 + mi * 16;
        int r2 = r1 + 8;
#pragma unroll
        for (int nf = 0; nf < 8; nf++) {
            int col = ccol0 + nf * 8;
            float b0 = bias[col], b1 = bias[col + 1];
#pragma unroll
            for (int half = 0; half < 2; half++) {
                int row = half ? r2 : r1;
                if (row >= N) continue;
                float sx = fmaxf(acc[mi][nf][half * 2 + 0] + b0, 0.f);
                float sy = fmaxf(acc[mi][nf][half * 2 + 1] + b1, 0.f);
                size_t o = (size_t)row * F + col;
                __nv_bfloat16 hx = __float2bfloat16(sx), hy = __float2bfloat16(sy);
                float lxf = sx - __bfloat162float(hx), lyf = sy - __bfloat162float(hy);
                __nv_bfloat162 th = __nv_bfloat162(hx, hy);
                __nv_bfloat162 tl = __nv_bfloat162(__float2bfloat16(lxf), __float2bfloat16(lyf));
                *(uint32_t*)(Ohi + o) = *(uint32_t*)&th;
                *(uint32_t*)(Olo + o) = *(uint32_t*)&tl;
            }
        }
    }
}

// ---------------------------------------------------------------------------
// Skinny tensor GEMM: z = r(rows x 256) @ G(256 x 16), fp32 out.
// ---------------------------------------------------------------------------
__global__ __launch_bounds__(256)
void zmma_kernel(const __nv_bfloat16* __restrict__ rhi,
                 const __nv_bfloat16* __restrict__ rlo,
                 float* __restrict__ z, int m0off, int N)
{
    __shared__ __nv_bfloat16 sAhi[128 * BKP];
    __shared__ __nv_bfloat16 sAlo[128 * BKP];
    __shared__ __nv_bfloat16 sBhi[16 * 264];
    __shared__ __nv_bfloat16 sBlo[16 * 264];

    const int tid = threadIdx.x;
    const int lane = tid & 31;
    const int w = tid >> 5;
    const int m0 = m0off + blockIdx.x * 128;

    const uint32_t aAhi = (uint32_t)__cvta_generic_to_shared(sAhi);
    const uint32_t aAlo = (uint32_t)__cvta_generic_to_shared(sAlo);
    const uint32_t aBhi = (uint32_t)__cvta_generic_to_shared(sBhi);
    const uint32_t aBlo = (uint32_t)__cvta_generic_to_shared(sBlo);

    for (int i = tid; i < 16 * 256; i += 256) {
        int n = i >> 8, k = i & 255;
        sBhi[n * 264 + k] = g_Ghi[i];
        sBlo[n * 264 + k] = g_Glo[i];
    }

    const int t  = lane >> 3;
    const int tr = lane & 7;
    const int a_row_l = w * 16 + (t & 1) * 8 + tr;
    const int a_koff  = (t >> 1) * 8;
    const int b_row_l = (t >> 1) * 8 + tr;
    const int b_koff  = (t & 1) * 8;

    const int crow = tid >> 1;
    const int cseg = (tid & 1) * 16;
    const int arow = m0 + crow;

    float acc[2][4];
#pragma unroll
    for (int nf = 0; nf < 2; nf++)
#pragma unroll
        for (int c = 0; c < 4; c++) acc[nf][c] = 0.f;

    for (int ch = 0; ch < 8; ch++) {
        const int k0 = ch * 32;
        uint4 vh = make_uint4(0, 0, 0, 0), vl = vh, vh2 = vh, vl2 = vh;
        if (arow < N) {
            const __nv_bfloat16* ph = rhi + (size_t)arow * 256 + k0 + cseg;
            const __nv_bfloat16* pl = rlo + (size_t)arow * 256 + k0 + cseg;
            vh = *(const uint4*)ph;  vh2 = *(const uint4*)(ph + 8);
            vl = *(const uint4*)pl;  vl2 = *(const uint4*)(pl + 8);
        }
        __syncthreads();
        *(uint4*)&sAhi[crow * BKP + cseg] = vh;
        *(uint4*)&sAhi[crow * BKP + cseg + 8] = vh2;
        *(uint4*)&sAlo[crow * BKP + cseg] = vl;
        *(uint4*)&sAlo[crow * BKP + cseg + 8] = vl2;
        __syncthreads();

#pragma unroll
        for (int s = 0; s < 2; s++) {
            const int kb = s * 16;
            uint32_t ahi[4], alo[4];
            uint32_t offA = (uint32_t)((a_row_l * BKP + kb + a_koff) * 2);
            ldsm4(ahi, aAhi + offA);
            ldsm4(alo, aAlo + offA);
            uint32_t bhi[2][2], blo[2][2];
            uint32_t offB = (uint32_t)((b_row_l * 264 + k0 + kb + b_koff) * 2);
            uint32_t r4[4];
            ldsm4(r4, aBhi + offB);
            bhi[0][0] = r4[0]; bhi[0][1] = r4[1];
            bhi[1][0] = r4[2]; bhi[1][1] = r4[3];
            ldsm4(r4, aBlo + offB);
            blo[0][0] = r4[0]; blo[0][1] = r4[1];
            blo[1][0] = r4[2]; blo[1][1] = r4[3];
#pragma unroll
            for (int nf = 0; nf < 2; nf++) {
                mma16816(acc[nf], ahi, bhi[nf]);
                mma16816(acc[nf], ahi, blo[nf]);
                mma16816(acc[nf], alo, bhi[nf]);
            }
        }
    }

    const int crow0 = m0 + w * 16 + (lane >> 2);
    const int ccol0 = (lane & 3) * 2;
#pragma unroll
    for (int nf = 0; nf < 2; nf++) {
        int col = ccol0 + nf * 8;
#pragma unroll
        for (int half = 0; half < 2; half++) {
            int row = crow0 + half * 8;
            if (row < N) {
                size_t o = (size_t)row * 16 + col;
                z[o]     = acc[nf][half * 2 + 0];
                z[o + 1] = acc[nf][half * 2 + 1];
            }
        }
    }
}

// ---------------------------------------------------------------------------
// aggx + xq fused, chunked: nodes [node0, nodeEnd)
// ---------------------------------------------------------------------------
__global__ __launch_bounds__(256)
void aggx_xq_kernel(const float* __restrict__ x,
                    __nv_bfloat16* __restrict__ Ohi, __nv_bfloat16* __restrict__ Olo,
                    float* __restrict__ y,
                    const float* __restrict__ dis, int node0, int nodeEnd)
{
    __shared__ float qsh[256];
    if (threadIdx.x < 256) qsh[threadIdx.x] = g_q[threadIdx.x];
    __syncthreads();

    const int lane = threadIdx.x & 31;
    const int node = node0 + ((blockIdx.x * blockDim.x + threadIdx.x) >> 5);
    if (node >= nodeEnd) return;

    int beg = g_rowptr[node];
    int end = g_rowptr[node + 1];

    float4 acc = make_float4(0.f, 0.f, 0.f, 0.f);
    for (int base = beg; base < end; base += 32) {
        int n = min(32, end - base);
        int srcReg = 0; float nrReg = 0.f;
        if (lane < n) {
            srcReg = g_csr_src[base + lane];
            nrReg  = g_csr_norm[base + lane];
        }
        for (int k = 0; k < n; k++) {
            int   r = __shfl_sync(0xffffffffu, srcReg, k);
            float wv = __shfl_sync(0xffffffffu, nrReg, k);
            float4 v = ((const float4*)(x + (size_t)r * 128))[lane];
            acc.x += wv * v.x; acc.y += wv * v.y;
            acc.z += wv * v.z; acc.w += wv * v.w;
        }
    }
    float dd = dis[node];
    float d2 = dd * dd;
    float4 sv = ((const float4*)(x + (size_t)node * 128))[lane];
    acc.x += d2 * sv.x; acc.y += d2 * sv.y;
    acc.z += d2 * sv.z; acc.w += d2 * sv.w;

    {
        int k4 = lane * 4;
        float a0 = sv.x * qsh[(k4 + 0) * 2] + sv.y * qsh[(k4 + 1) * 2]
                 + sv.z * qsh[(k4 + 2) * 2] + sv.w * qsh[(k4 + 3) * 2];
        float a1 = sv.x * qsh[(k4 + 0) * 2 + 1] + sv.y * qsh[(k4 + 1) * 2 + 1]
                 + sv.z * qsh[(k4 + 2) * 2 + 1] + sv.w * qsh[(k4 + 3) * 2 + 1];
#pragma unroll
        for (int off = 16; off; off >>= 1) {
            a0 += __shfl_xor_sync(0xffffffffu, a0, off);
            a1 += __shfl_xor_sync(0xffffffffu, a1, off);
        }
        if (lane == 0) {
            y[(size_t)node * 2] = a0;
            y[(size_t)node * 2 + 1] = a1;
        }
    }

    size_t o = (size_t)node * 128 + lane * 4;
    __nv_bfloat16 h0 = __float2bfloat16(acc.x), h1 = __float2bfloat16(acc.y);
    __nv_bfloat16 h2 = __float2bfloat16(acc.z), h3 = __float2bfloat16(acc.w);
    __nv_bfloat162 t01 = __nv_bfloat162(h0, h1), t23 = __nv_bfloat162(h2, h3);
    __nv_bfloat162 l01 = __nv_bfloat162(__float2bfloat16(acc.x - __bfloat162float(h0)),
                                        __float2bfloat16(acc.y - __bfloat162float(h1)));
    __nv_bfloat162 l23 = __nv_bfloat162(__float2bfloat16(acc.z - __bfloat162float(h2)),
                                        __float2bfloat16(acc.w - __bfloat162float(h3)));
    uint2 ph, pl;
    ph.x = *(uint32_t*)&t01; ph.y = *(uint32_t*)&t23;
    pl.x = *(uint32_t*)&l01; pl.y = *(uint32_t*)&l23;
    *(uint2*)(Ohi + o) = ph;
    *(uint2*)(Olo + o) = pl;
}

// ---------------------------------------------------------------------------
// prop16: out = M z + c0
// ---------------------------------------------------------------------------
__global__ __launch_bounds__(256)
void prop16_kernel(const float* __restrict__ z, float* __restrict__ outp,
                   const float* __restrict__ dis, int N)
{
    const int lane = threadIdx.x & 31;
    const int node = (blockIdx.x * blockDim.x + threadIdx.x) >> 5;
    if (node >= N) return;

    int beg = g_rowptr[node];
    int end = g_rowptr[node + 1];
    int hw = lane >> 4, f = lane & 15;

    float acc = 0.f;
    for (int e = beg + hw; e < end; e += 2) {
        int r = g_csr_src[e];
        float wv = g_csr_norm[e];
        acc += wv * z[(size_t)r * 16 + f];
    }
    acc += __shfl_xor_sync(0xffffffffu, acc, 16);
    if (hw == 0) {
        float dd = dis[node];
        outp[(size_t)node * 16 + f] = acc + dd * dd * z[(size_t)node * 16 + f] + g_c0[f];
    }
}

// ---------------------------------------------------------------------------
// prop2: v' = M v + s_k ; LAST applies sigmoid
// ---------------------------------------------------------------------------
template <bool LAST>
__global__ __launch_bounds__(256)
void prop2_kernel(const float* __restrict__ vin, float* __restrict__ vout,
                  const float* __restrict__ dis, float* __restrict__ outp,
                  int sidx, int N)
{
    const int lane = threadIdx.x & 31;
    const int node = (blockIdx.x * blockDim.x + threadIdx.x) >> 5;
    if (node >= N) return;

    int beg = g_rowptr[node];
    int end = g_rowptr[node + 1];

    float p0 = 0.f, p1 = 0.f;
    for (int e = beg + lane; e < end; e += 32) {
        int r = g_csr_src[e];
        float wv = g_csr_norm[e];
        float2 v = *(const float2*)(vin + (size_t)r * 2);
        p0 += wv * v.x;
        p1 += wv * v.y;
    }
#pragma unroll
    for (int off = 16; off; off >>= 1) {
        p0 += __shfl_xor_sync(0xffffffffu, p0, off);
        p1 += __shfl_xor_sync(0xffffffffu, p1, off);
    }
    if (lane == 0) {
        float dd = dis[node];
        float d2 = dd * dd;
        float2 sv = *(const float2*)(vin + (size_t)node * 2);
        float r0 = p0 + d2 * sv.x + g_s[sidx][0];
        float r1 = p1 + d2 * sv.y + g_s[sidx][1];
        if (LAST) {
            outp[(size_t)node * 2]     = 1.f / (1.f + expf(-r0));
            outp[(size_t)node * 2 + 1] = 1.f / (1.f + expf(-r1));
        } else {
            vout[(size_t)node * 2]     = r0;
            vout[(size_t)node * 2 + 1] = r1;
        }
    }
}

// ---------------------------------------------------------------------------
// Launch — chunked aggx→GEMM→zmma pipeline across streams + encoder overlap
// ---------------------------------------------------------------------------
extern "C" void kernel_launch(void* const* d_in, const int* in_sizes, int n_in,
                              void* d_out, int out_size)
{
    const float* x = (const float*)d_in[0];
    const void* ei = d_in[1];
    const float* W1  = (const float*)d_in[2];
    const float* b1  = (const float*)d_in[3];
    const float* W2  = (const float*)d_in[4];
    const float* b2  = (const float*)d_in[5];
    const float* Wc  = (const float*)d_in[6];
    const float* bc  = (const float*)d_in[7];
    const float* We1 = (const float*)d_in[8];
    const float* be1 = (const float*)d_in[9];
    const float* We2 = (const float*)d_in[10];
    const float* be2 = (const float*)d_in[11];
    const float* We3 = (const float*)d_in[12];
    const float* be3 = (const float*)d_in[13];
    const float* We4 = (const float*)d_in[14];
    const float* be4 = (const float*)d_in[15];
    const float* Wt  = (const float*)d_in[16];
    const float* bt  = (const float*)d_in[17];
    float* out = (float*)d_out;

    const int N = in_sizes[0] / 128;
    const int E = in_sizes[1] / 2;
    const int nscan = (N + SCAN_BS - 1) / SCAN_BS;

    float *dis, *z, *y, *y2;
    __nv_bfloat16 *whi, *wlo, *pDhi, *pDlo, *pAhi, *pAlo;
    cudaGetSymbolAddress((void**)&dis, g_dis);
    cudaGetSymbolAddress((void**)&z, g_z);
    cudaGetSymbolAddress((void**)&y, g_y);
    cudaGetSymbolAddress((void**)&y2, g_y2);
    cudaGetSymbolAddress((void**)&whi, g_whi);
    cudaGetSymbolAddress((void**)&wlo, g_wlo);
    cudaGetSymbolAddress((void**)&pDhi, g_pDhi);
    cudaGetSymbolAddress((void**)&pDlo, g_pDlo);
    cudaGetSymbolAddress((void**)&pAhi, g_pAhi);
    cudaGetSymbolAddress((void**)&pAlo, g_pAlo);

    cudaFuncSetAttribute(mma_gemm_kernel, cudaFuncAttributeMaxDynamicSharedMemorySize, GEMM_SMEM);

    // One-time streams + events (created on the first, non-captured call)
    static cudaStream_t s2 = nullptr, s3 = nullptr;
    static cudaEvent_t evS = nullptr, evW = nullptr, evB = nullptr, evZ = nullptr;
    static cudaEvent_t evAg[NCHUNK];
    if (!s2) {
        cudaStreamCreateWithFlags(&s2, cudaStreamNonBlocking);
        cudaStreamCreateWithFlags(&s3, cudaStreamNonBlocking);
        cudaEventCreateWithFlags(&evS, cudaEventDisableTiming);
        cudaEventCreateWithFlags(&evW, cudaEventDisableTiming);
        cudaEventCreateWithFlags(&evB, cudaEventDisableTiming);
        cudaEventCreateWithFlags(&evZ, cudaEventDisableTiming);
        for (int c = 0; c < NCHUNK; c++) cudaEventCreateWithFlags(&evAg[c], cudaEventDisableTiming);
    }

    // --- fork: weight prep on s2 ---
    cudaEventRecord(evS, 0);
    cudaStreamWaitEvent(s2, evS, 0);
    cudaStreamWaitEvent(s3, evS, 0);
    conv_w_kernel<<<128, 256, 0, s2>>>(W1);
    gwc_kernel<<<16, 256, 0, s2>>>(W2, Wc, b2, bc);
    enc_chain_kernel<<<1, 256, 0, s2>>>(We1, We2, We3, We4, Wt, be1, be2, be3, be4, bt);
    cudaEventRecord(evW, s2);

    // --- edge preprocessing on default stream ---
    init_kernel<<<(N + 255) / 256, 256>>>(ei, N);
    count_kernel<<<(E + 255) / 256, 256>>>(ei, E);
    scan_blocks_kernel<<<nscan, SCAN_BS>>>(N);
    scan_tops_kernel<<<1, 512>>>(nscan);
    scan_add_fin_kernel<<<nscan, SCAN_BS>>>(N, E);
    fill_csr_kernel<<<(E + 255) / 256, 256>>>(ei, E);

    // --- chunked aggx (default) feeding GEMM+zmma (s3) ---
    cudaStreamWaitEvent(0, evW, 0);   // aggx needs q
    const int chunkN = (((N + NCHUNK - 1) / NCHUNK) + 127) & ~127;
    for (int c = 0; c < NCHUNK; c++) {
        int n0 = c * chunkN;
        if (n0 >= N) { cudaEventRecord(evAg[c], 0); continue; }
        int n1 = min(n0 + chunkN, N);
        int cnt = n1 - n0;
        aggx_xq_kernel<<<(cnt + 7) / 8, 256>>>(x, pDhi, pDlo, y, dis, n0, n1);
        cudaEventRecord(evAg[c], 0);

        cudaStreamWaitEvent(s3, evAg[c], 0);
        dim3 gw((cnt + 127) / 128, 2);
        mma_gemm_kernel<<<gw, 256, GEMM_SMEM, s3>>>(pDhi, pDlo, whi, wlo, b1,
                                                    pAhi, pAlo, n0, N, 128, 256);
        zmma_kernel<<<(cnt + 127) / 128, 256, 0, s3>>>(pAhi, pAlo, z, n0, N);
    }
    cudaEventRecord(evZ, s3);

    // --- encoder chain on s2 after all y written (last aggx chunk) ---
    cudaStreamWaitEvent(s2, evAg[NCHUNK - 1], 0);
    const int AGG_BLOCKS = (N + 7) / 8;
    prop2_kernel<false><<<AGG_BLOCKS, 256, 0, s2>>>(y, y2, dis, nullptr, 0, N);
    prop2_kernel<false><<<AGG_BLOCKS, 256, 0, s2>>>(y2, y, dis, nullptr, 1, N);
    prop2_kernel<false><<<AGG_BLOCKS, 256, 0, s2>>>(y, y2, dis, nullptr, 2, N);
    prop2_kernel<true><<<AGG_BLOCKS, 256, 0, s2>>>(y2, nullptr, dis, out + (size_t)N * 16, 3, N);
    cudaEventRecord(evB, s2);

    // --- final prop16 on default after all z chunks ---
    cudaStreamWaitEvent(0, evZ, 0);
    prop16_kernel<<<AGG_BLOCKS, 256>>>(z, out, dis, N);

    // join encoder branch
    cudaStreamWaitEvent(0, evB, 0);
}

// round 17
// speedup vs baseline: 1.3705x; 1.3705x over previous
#include <cuda_runtime.h>
#include <cuda_bf16.h>
#include <cstdint>
#include <math.h>

#define NNODES 100000
#define NEDGES 1600000
#define SCAN_BS 256
#define BKP 40
#define ARR (128 * BKP)
#define GEMM_SMEM (2 * 4 * ARR * 2)   // 81920 B

// ---------------------------------------------------------------------------
// Scratch (device globals)
// ---------------------------------------------------------------------------
__device__ float g_dis[NNODES];
__device__ __nv_bfloat16 g_pDhi[(size_t)NNODES * 128], g_pDlo[(size_t)NNODES * 128]; // aggx split
__device__ float g_z[(size_t)NNODES * 16];
__device__ float g_y[(size_t)NNODES * 2];
__device__ float g_y2[(size_t)NNODES * 2];
__device__ int   g_cnt[NNODES];
__device__ int   g_cur[NNODES];
__device__ int   g_rowptr[NNODES + 1];
__device__ int   g_btot[(NNODES + SCAN_BS - 1) / SCAN_BS + 1];
__device__ int   g_boff[(NNODES + SCAN_BS - 1) / SCAN_BS + 1];
__device__ int   g_csr_src[NEDGES];
__device__ float g_csr_norm[NEDGES];
__device__ int   g_is64;
__device__ __nv_bfloat16 g_whi[32768], g_wlo[32768];   // W1 [n][k] split
__device__ __nv_bfloat16 g_Ghi[4096], g_Glo[4096];     // G=W2Wc [j][k=256] split
__device__ float g_c0[16];
__device__ float g_q[256];
__device__ float g_s[4][2];

// ---------------------------------------------------------------------------
// Preprocessing
// ---------------------------------------------------------------------------
__global__ void init_kernel(const void* ei_raw, int N) {
    int i = blockIdx.x * blockDim.x + threadIdx.x;
    if (i < N) { g_cnt[i] = 0; g_cur[i] = 0; }
    if (i == 0) {
        const long long* p = (const long long*)ei_raw;
        int ok = 1;
        for (int k = 0; k < 8; k++) {
            long long v = p[k];
            if (v < 0 || v >= (long long)N) ok = 0;
        }
        g_is64 = ok;
    }
}

__global__ void zero_z_kernel(int N) {
    int i = blockIdx.x * blockDim.x + threadIdx.x;
    if (i < N * 16) g_z[i] = 0.f;
}

__global__ void count_kernel(const void* ei_raw, int E) {
    int e = blockIdx.x * blockDim.x + threadIdx.x;
    if (e >= E) return;
    int c;
    if (g_is64) {
        const long long* p = (const long long*)ei_raw;
        c = (int)p[(size_t)E + e];
    } else {
        const int* p = (const int*)ei_raw;
        c = p[E + e];
    }
    atomicAdd(&g_cnt[c], 1);
}

__global__ void scan_blocks_kernel(int N) {
    __shared__ int s[SCAN_BS];
    int i = blockIdx.x * SCAN_BS + threadIdx.x;
    int v = (i < N) ? g_cnt[i] : 0;
    s[threadIdx.x] = v;
    __syncthreads();
    for (int off = 1; off < SCAN_BS; off <<= 1) {
        int t = (threadIdx.x >= off) ? s[threadIdx.x - off] : 0;
        __syncthreads();
        s[threadIdx.x] += t;
        __syncthreads();
    }
    if (i < N) g_rowptr[i] = s[threadIdx.x] - v;
    if (threadIdx.x == SCAN_BS - 1) g_btot[blockIdx.x] = s[SCAN_BS - 1];
}

__global__ void scan_tops_kernel(int nblocks) {
    __shared__ int s[512];
    int v = (threadIdx.x < nblocks) ? g_btot[threadIdx.x] : 0;
    s[threadIdx.x] = v;
    __syncthreads();
    for (int off = 1; off < 512; off <<= 1) {
        int t = (threadIdx.x >= off) ? s[threadIdx.x - off] : 0;
        __syncthreads();
        s[threadIdx.x] += t;
        __syncthreads();
    }
    if (threadIdx.x < nblocks) g_boff[threadIdx.x] = s[threadIdx.x] - v;
}

__global__ void scan_add_fin_kernel(int N, int E) {
    int i = blockIdx.x * SCAN_BS + threadIdx.x;
    if (i < N) {
        g_rowptr[i] += g_boff[blockIdx.x];
        g_dis[i] = rsqrtf((float)g_cnt[i] + 1.0f);
    }
    if (i == 0) g_rowptr[N] = E;
}

__global__ void fill_csr_kernel(const void* ei_raw, int E) {
    int e = blockIdx.x * blockDim.x + threadIdx.x;
    if (e >= E) return;
    int r, c;
    if (g_is64) {
        const long long* p = (const long long*)ei_raw;
        r = (int)p[e];
        c = (int)p[(size_t)E + e];
    } else {
        const int* p = (const int*)ei_raw;
        r = p[e];
        c = p[E + e];
    }
    int pos = g_rowptr[c] + atomicAdd(&g_cur[c], 1);
    g_csr_src[pos] = r;
    g_csr_norm[pos] = g_dis[r] * g_dis[c];
}

// W1 [K=128][F=256] fp32 -> whi/wlo [F][K] bf16
__global__ void conv_w_kernel(const float* __restrict__ W) {
    int idx = blockIdx.x * blockDim.x + threadIdx.x;
    if (idx >= 128 * 256) return;
    int k = idx / 256;
    int n = idx % 256;
    float wv = W[idx];
    __nv_bfloat16 h = __float2bfloat16(wv);
    g_whi[n * 128 + k] = h;
    g_wlo[n * 128 + k] = __float2bfloat16(wv - __bfloat162float(h));
}

// G = W2 @ Wc (256x16) -> split [j][k]; c0 = b2ᵀWc + bc
__global__ void gwc_kernel(const float* __restrict__ W2, const float* __restrict__ Wc,
                           const float* __restrict__ b2, const float* __restrict__ bc) {
    int j = blockIdx.x;
    int m = threadIdx.x;
    float s = 0.f;
    for (int k = 0; k < 128; k++) s += W2[m * 128 + k] * Wc[k * 16 + j];
    __nv_bfloat16 h = __float2bfloat16(s);
    g_Ghi[j * 256 + m] = h;
    g_Glo[j * 256 + m] = __float2bfloat16(s - __bfloat162float(h));
    if (m == 0) {
        float c = 0.f;
        for (int k = 0; k < 128; k++) c += b2[k] * Wc[k * 16 + j];
        g_c0[j] = c + bc[j];
    }
}

// Encoder weight chain
__global__ void enc_chain_kernel(const float* We1, const float* We2, const float* We3,
                                 const float* We4, const float* Wt,
                                 const float* be1, const float* be2, const float* be3,
                                 const float* be4, const float* bt) {
    __shared__ float a[256], b[256];
    int tid = threadIdx.x;
    int row = tid >> 1, j = tid & 1;
    float s;

    s = 0.f;
    for (int k = 0; k < 128; k++) s += We4[row * 128 + k] * Wt[k * 2 + j];
    a[tid] = s;
    __syncthreads();

    if (tid < 2) {
        float acc = 0.f;
        for (int k = 0; k < 128; k++) acc += be3[k] * a[k * 2 + tid];
        g_s[2][tid] = acc;
        float a4 = 0.f;
        for (int k = 0; k < 128; k++) a4 += be4[k] * Wt[k * 2 + tid];
        g_s[3][tid] = a4 + bt[tid];
    }
    s = 0.f;
    for (int k = 0; k < 128; k++) s += We3[row * 128 + k] * a[k * 2 + j];
    b[tid] = s;
    __syncthreads();

    if (tid < 2) {
        float acc = 0.f;
        for (int k = 0; k < 128; k++) acc += be2[k] * b[k * 2 + tid];
        g_s[1][tid] = acc;
    }
    s = 0.f;
    for (int k = 0; k < 128; k++) s += We2[row * 128 + k] * b[k * 2 + j];
    __syncthreads();
    a[tid] = s;
    __syncthreads();

    if (tid < 2) {
        float acc = 0.f;
        for (int k = 0; k < 128; k++) acc += be1[k] * a[k * 2 + tid];
        g_s[0][tid] = acc;
    }
    s = 0.f;
    for (int k = 0; k < 128; k++) s += We1[row * 128 + k] * a[k * 2 + j];
    g_q[tid] = s;
}

// ---------------------------------------------------------------------------
// PTX helpers
// ---------------------------------------------------------------------------
__device__ __forceinline__ void mma16816(float* d, const uint32_t* a, const uint32_t* b) {
    asm volatile("mma.sync.aligned.m16n8k16.row.col.f32.bf16.bf16.f32 "
        "{%0,%1,%2,%3}, {%4,%5,%6,%7}, {%8,%9}, {%0,%1,%2,%3};"
        : "+f"(d[0]), "+f"(d[1]), "+f"(d[2]), "+f"(d[3])
        : "r"(a[0]), "r"(a[1]), "r"(a[2]), "r"(a[3]), "r"(b[0]), "r"(b[1]));
}
__device__ __forceinline__ void ldsm4(uint32_t* r, uint32_t addr) {
    asm volatile("ldmatrix.sync.aligned.m8n8.x4.shared.b16 {%0,%1,%2,%3}, [%4];"
        : "=r"(r[0]), "=r"(r[1]), "=r"(r[2]), "=r"(r[3]) : "r"(addr));
}
__device__ __forceinline__ void cpa16(uint32_t dst, const __nv_bfloat16* src, int bytes) {
    asm volatile("cp.async.cg.shared.global [%0], [%1], 16, %2;"
                 :: "r"(dst), "l"(src), "r"(bytes));
}
__device__ __forceinline__ uint32_t packhi2(float a, float b) {
    __nv_bfloat162 t = __nv_bfloat162(__float2bfloat16(a), __float2bfloat16(b));
    return *(uint32_t*)&t;
}
__device__ __forceinline__ void red2(float* addr, float v0, float v1) {
    asm volatile("red.global.add.v2.f32 [%0], {%1,%2};"
                 :: "l"(addr), "f"(v0), "f"(v1) : "memory");
}

// ---------------------------------------------------------------------------
// Fused GEMM + z epilogue:
//   r = relu(aggx @ W1 + b1)  (in registers, hi/lo 3-pass bf16 MMA)
//   z += r_tile @ G[n0:n0+128][16]   (in-register MMA, red.global.add)
// CTA tile 128x128, BK=32, 8 warps 4(m)x2(n).
// ---------------------------------------------------------------------------
#define GSTR 136   // smem stride for staged G (128 + 8)

__global__ __launch_bounds__(256, 2)
void gemm_z_kernel(const __nv_bfloat16* __restrict__ Ahi_g,
                   const __nv_bfloat16* __restrict__ Alo_g,
                   const __nv_bfloat16* __restrict__ whi,
                   const __nv_bfloat16* __restrict__ wlo,
                   const float* __restrict__ bias,
                   float* __restrict__ z,
                   int N, int K)
{
    extern __shared__ __nv_bfloat16 sm[];
    const uint32_t smBase = (uint32_t)__cvta_generic_to_shared(sm);

    const int tid = threadIdx.x;
    const int lane = tid & 31;
    const int w = tid >> 5;
    const int wm = w >> 1;
    const int wn = w & 1;
    const int m0 = blockIdx.x * 128;
    const int n0 = blockIdx.y * 128;

    const int crow = tid >> 1;
    const int cseg = (tid & 1) * 16;
    const int arow = m0 + crow;
    const int aval = (arow < N) ? 16 : 0;
    const int arowc = (arow < N) ? arow : 0;
    const __nv_bfloat16* aHi = Ahi_g + (size_t)arowc * K;
    const __nv_bfloat16* aLo = Alo_g + (size_t)arowc * K;
    const __nv_bfloat16* bHi = whi + (size_t)(n0 + crow) * K;
    const __nv_bfloat16* bLo = wlo + (size_t)(n0 + crow) * K;

#define LOAD_STAGE(st, k0) do {                                                  \
    uint32_t b_ = smBase + (uint32_t)(st) * (4 * ARR * 2);                       \
    uint32_t dA = b_ + (uint32_t)(crow * BKP + cseg) * 2;                        \
    cpa16(dA,                aHi + (k0) + cseg,     aval);                       \
    cpa16(dA + 16,           aHi + (k0) + cseg + 8, aval);                       \
    cpa16(dA + ARR * 2,      aLo + (k0) + cseg,     aval);                       \
    cpa16(dA + ARR * 2 + 16, aLo + (k0) + cseg + 8, aval);                       \
    cpa16(dA + 2 * ARR * 2,      bHi + (k0) + cseg,     16);                     \
    cpa16(dA + 2 * ARR * 2 + 16, bHi + (k0) + cseg + 8, 16);                     \
    cpa16(dA + 3 * ARR * 2,      bLo + (k0) + cseg,     16);                     \
    cpa16(dA + 3 * ARR * 2 + 16, bLo + (k0) + cseg + 8, 16);                     \
    asm volatile("cp.async.commit_group;");                                      \
} while (0)

    const int t  = lane >> 3;
    const int tr = lane & 7;
    const int a_row_l = wm * 32 + (t & 1) * 8 + tr;
    const int a_koff  = (t >> 1) * 8;
    const int b_row_l = wn * 64 + (t >> 1) * 8 + tr;
    const int b_koff  = (t & 1) * 8;

    float acc[2][8][4];
#pragma unroll
    for (int mi = 0; mi < 2; mi++)
#pragma unroll
        for (int nf = 0; nf < 8; nf++)
#pragma unroll
            for (int c = 0; c < 4; c++) acc[mi][nf][c] = 0.f;

    const int nch = K >> 5;
    LOAD_STAGE(0, 0);

    for (int ch = 0; ch < nch; ch++) {
        if (ch + 1 < nch) {
            LOAD_STAGE((ch + 1) & 1, (ch + 1) << 5);
            asm volatile("cp.async.wait_group 1;");
        } else {
            asm volatile("cp.async.wait_group 0;");
        }
        __syncthreads();

        const uint32_t sb = smBase + (uint32_t)(ch & 1) * (4 * ARR * 2);
        const uint32_t aAhi = sb;
        const uint32_t aAlo = sb + ARR * 2;
        const uint32_t aBhi = sb + 2 * ARR * 2;
        const uint32_t aBlo = sb + 3 * ARR * 2;

#pragma unroll
        for (int s = 0; s < 2; s++) {
            const int kb = s * 16;
            uint32_t ahi[2][4], alo[2][4];
#pragma unroll
            for (int mi = 0; mi < 2; mi++) {
                uint32_t off = (uint32_t)(((a_row_l + mi * 16) * BKP + kb + a_koff) * 2);
                ldsm4(ahi[mi], aAhi + off);
                ldsm4(alo[mi], aAlo + off);
            }
            uint32_t bhi[8][2], blo[8][2];
#pragma unroll
            for (int q = 0; q < 4; q++) {
                uint32_t off = (uint32_t)(((b_row_l + q * 16) * BKP + kb + b_koff) * 2);
                uint32_t r4[4];
                ldsm4(r4, aBhi + off);
                bhi[2 * q][0] = r4[0]; bhi[2 * q][1] = r4[1];
                bhi[2 * q + 1][0] = r4[2]; bhi[2 * q + 1][1] = r4[3];
                ldsm4(r4, aBlo + off);
                blo[2 * q][0] = r4[0]; blo[2 * q][1] = r4[1];
                blo[2 * q + 1][0] = r4[2]; blo[2 * q + 1][1] = r4[3];
            }
#pragma unroll
            for (int mi = 0; mi < 2; mi++)
#pragma unroll
                for (int nf = 0; nf < 8; nf++) {
                    mma16816(acc[mi][nf], ahi[mi], bhi[nf]);
                    mma16816(acc[mi][nf], ahi[mi], blo[nf]);
                    mma16816(acc[mi][nf], alo[mi], bhi[nf]);
                }
        }
        __syncthreads();
    }
#undef LOAD_STAGE

    // ---- r = relu(acc + bias) in place ----
    const int colbase = n0 + wn * 64 + (lane & 3) * 2;
#pragma unroll
    for (int nf = 0; nf < 8; nf++) {
        int col = colbase + nf * 8;
        float b0 = bias[col], b1 = bias[col + 1];
#pragma unroll
        for (int mi = 0; mi < 2; mi++) {
            acc[mi][nf][0] = fmaxf(acc[mi][nf][0] + b0, 0.f);
            acc[mi][nf][1] = fmaxf(acc[mi][nf][1] + b1, 0.f);
            acc[mi][nf][2] = fmaxf(acc[mi][nf][2] + b0, 0.f);
            acc[mi][nf][3] = fmaxf(acc[mi][nf][3] + b1, 0.f);
        }
    }

    // ---- stage G[16][128 local] hi/lo into smem (stride GSTR) ----
    __nv_bfloat16* sGhi = sm;                       // 16*GSTR
    __nv_bfloat16* sGlo = sm + 16 * GSTR;
    for (int i = tid; i < 16 * 128; i += 256) {
        int j = i >> 7, k = i & 127;
        sGhi[j * GSTR + k] = g_Ghi[j * 256 + n0 + k];
        sGlo[j * GSTR + k] = g_Glo[j * 256 + n0 + k];
    }
    __syncthreads();
    const uint32_t aGhi = smBase;
    const uint32_t aGlo = smBase + (uint32_t)(16 * GSTR * 2);

    // ---- z partial: zacc = r(m x 64) @ G(64 x 16), hi/lo 3-pass ----
    float zacc[2][2][4];
#pragma unroll
    for (int mi = 0; mi < 2; mi++)
#pragma unroll
        for (int jn = 0; jn < 2; jn++)
#pragma unroll
            for (int c = 0; c < 4; c++) zacc[mi][jn][c] = 0.f;

    const int gb_row = (t >> 1) * 8 + tr;     // j row for ldmatrix
    const int gb_koff = (t & 1) * 8;
#pragma unroll
    for (int s = 0; s < 4; s++) {
        int klocal = wn * 64 + s * 16;
        uint32_t offG = (uint32_t)((gb_row * GSTR + klocal + gb_koff) * 2);
        uint32_t gh4[4], gl4[4];
        ldsm4(gh4, aGhi + offG);
        ldsm4(gl4, aGlo + offG);
        uint32_t gbhi[2][2] = {{gh4[0], gh4[1]}, {gh4[2], gh4[3]}};
        uint32_t gblo[2][2] = {{gl4[0], gl4[1]}, {gl4[2], gl4[3]}};

#pragma unroll
        for (int mi = 0; mi < 2; mi++) {
            // A fragment from acc[mi][2s], acc[mi][2s+1]
            float v[8] = { acc[mi][2 * s][0], acc[mi][2 * s][1],
                           acc[mi][2 * s][2], acc[mi][2 * s][3],
                           acc[mi][2 * s + 1][0], acc[mi][2 * s + 1][1],
                           acc[mi][2 * s + 1][2], acc[mi][2 * s + 1][3] };
            uint32_t rahi[4], ralo[4];
#pragma unroll
            for (int p = 0; p < 4; p++) {
                float v0 = v[2 * p], v1 = v[2 * p + 1];
                __nv_bfloat16 h0 = __float2bfloat16(v0), h1 = __float2bfloat16(v1);
                __nv_bfloat162 th = __nv_bfloat162(h0, h1);
                rahi[p] = *(uint32_t*)&th;
                __nv_bfloat162 tl = __nv_bfloat162(__float2bfloat16(v0 - __bfloat162float(h0)),
                                                   __float2bfloat16(v1 - __bfloat162float(h1)));
                ralo[p] = *(uint32_t*)&tl;
            }
#pragma unroll
            for (int jn = 0; jn < 2; jn++) {
                mma16816(zacc[mi][jn], rahi, gbhi[jn]);
                mma16816(zacc[mi][jn], rahi, gblo[jn]);
                mma16816(zacc[mi][jn], ralo, gbhi[jn]);
            }
        }
    }

    // ---- red.global.add z partials ----
    const int zrow0 = m0 + wm * 32 + (lane >> 2);
    const int zcol = (lane & 3) * 2;
#pragma unroll
    for (int mi = 0; mi < 2; mi++) {
        int r1 = zrow0 + mi * 16;
        int r2 = r1 + 8;
#pragma unroll
        for (int jn = 0; jn < 2; jn++) {
            int col = jn * 8 + zcol;
            if (r1 < N) red2(z + (size_t)r1 * 16 + col, zacc[mi][jn][0], zacc[mi][jn][1]);
            if (r2 < N) red2(z + (size_t)r2 * 16 + col, zacc[mi][jn][2], zacc[mi][jn][3]);
        }
    }
}

// ---------------------------------------------------------------------------
// aggx + xq fused: split(M x) and y = x[node]ᵀ q   (warp per node)
// ---------------------------------------------------------------------------
__global__ __launch_bounds__(256)
void aggx_xq_kernel(const float* __restrict__ x,
                    __nv_bfloat16* __restrict__ Ohi, __nv_bfloat16* __restrict__ Olo,
                    float* __restrict__ y,
                    const float* __restrict__ dis, int N)
{
    __shared__ float qsh[256];
    if (threadIdx.x < 256) qsh[threadIdx.x] = g_q[threadIdx.x];
    __syncthreads();

    const int lane = threadIdx.x & 31;
    const int node = (blockIdx.x * blockDim.x + threadIdx.x) >> 5;
    if (node >= N) return;

    int beg = g_rowptr[node];
    int end = g_rowptr[node + 1];

    float4 acc = make_float4(0.f, 0.f, 0.f, 0.f);
    for (int base = beg; base < end; base += 32) {
        int n = min(32, end - base);
        int srcReg = 0; float nrReg = 0.f;
        if (lane < n) {
            srcReg = g_csr_src[base + lane];
            nrReg  = g_csr_norm[base + lane];
        }
        for (int k = 0; k < n; k++) {
            int   r = __shfl_sync(0xffffffffu, srcReg, k);
            float wv = __shfl_sync(0xffffffffu, nrReg, k);
            float4 v = ((const float4*)(x + (size_t)r * 128))[lane];
            acc.x += wv * v.x; acc.y += wv * v.y;
            acc.z += wv * v.z; acc.w += wv * v.w;
        }
    }
    float dd = dis[node];
    float d2 = dd * dd;
    float4 sv = ((const float4*)(x + (size_t)node * 128))[lane];
    acc.x += d2 * sv.x; acc.y += d2 * sv.y;
    acc.z += d2 * sv.z; acc.w += d2 * sv.w;

    {
        int k4 = lane * 4;
        float a0 = sv.x * qsh[(k4 + 0) * 2] + sv.y * qsh[(k4 + 1) * 2]
                 + sv.z * qsh[(k4 + 2) * 2] + sv.w * qsh[(k4 + 3) * 2];
        float a1 = sv.x * qsh[(k4 + 0) * 2 + 1] + sv.y * qsh[(k4 + 1) * 2 + 1]
                 + sv.z * qsh[(k4 + 2) * 2 + 1] + sv.w * qsh[(k4 + 3) * 2 + 1];
#pragma unroll
        for (int off = 16; off; off >>= 1) {
            a0 += __shfl_xor_sync(0xffffffffu, a0, off);
            a1 += __shfl_xor_sync(0xffffffffu, a1, off);
        }
        if (lane == 0) {
            y[(size_t)node * 2] = a0;
            y[(size_t)node * 2 + 1] = a1;
        }
    }

    size_t o = (size_t)node * 128 + lane * 4;
    __nv_bfloat16 h0 = __float2bfloat16(acc.x), h1 = __float2bfloat16(acc.y);
    __nv_bfloat16 h2 = __float2bfloat16(acc.z), h3 = __float2bfloat16(acc.w);
    __nv_bfloat162 t01 = __nv_bfloat162(h0, h1), t23 = __nv_bfloat162(h2, h3);
    __nv_bfloat162 l01 = __nv_bfloat162(__float2bfloat16(acc.x - __bfloat162float(h0)),
                                        __float2bfloat16(acc.y - __bfloat162float(h1)));
    __nv_bfloat162 l23 = __nv_bfloat162(__float2bfloat16(acc.z - __bfloat162float(h2)),
                                        __float2bfloat16(acc.w - __bfloat162float(h3)));
    uint2 ph, pl;
    ph.x = *(uint32_t*)&t01; ph.y = *(uint32_t*)&t23;
    pl.x = *(uint32_t*)&l01; pl.y = *(uint32_t*)&l23;
    *(uint2*)(Ohi + o) = ph;
    *(uint2*)(Olo + o) = pl;
}

// ---------------------------------------------------------------------------
// prop16: out = M z + c0
// ---------------------------------------------------------------------------
__global__ __launch_bounds__(256)
void prop16_kernel(const float* __restrict__ z, float* __restrict__ outp,
                   const float* __restrict__ dis, int N)
{
    const int lane = threadIdx.x & 31;
    const int node = (blockIdx.x * blockDim.x + threadIdx.x) >> 5;
    if (node >= N) return;

    int beg = g_rowptr[node];
    int end = g_rowptr[node + 1];
    int hw = lane >> 4, f = lane & 15;

    float acc = 0.f;
    for (int e = beg + hw; e < end; e += 2) {
        int r = g_csr_src[e];
        float wv = g_csr_norm[e];
        acc += wv * z[(size_t)r * 16 + f];
    }
    acc += __shfl_xor_sync(0xffffffffu, acc, 16);
    if (hw == 0) {
        float dd = dis[node];
        outp[(size_t)node * 16 + f] = acc + dd * dd * z[(size_t)node * 16 + f] + g_c0[f];
    }
}

// ---------------------------------------------------------------------------
// prop2: v' = M v + s_k ; LAST applies sigmoid
// ---------------------------------------------------------------------------
template <bool LAST>
__global__ __launch_bounds__(256)
void prop2_kernel(const float* __restrict__ vin, float* __restrict__ vout,
                  const float* __restrict__ dis, float* __restrict__ outp,
                  int sidx, int N)
{
    const int lane = threadIdx.x & 31;
    const int node = (blockIdx.x * blockDim.x + threadIdx.x) >> 5;
    if (node >= N) return;

    int beg = g_rowptr[node];
    int end = g_rowptr[node + 1];

    float p0 = 0.f, p1 = 0.f;
    for (int e = beg + lane; e < end; e += 32) {
        int r = g_csr_src[e];
        float wv = g_csr_norm[e];
        float2 v = *(const float2*)(vin + (size_t)r * 2);
        p0 += wv * v.x;
        p1 += wv * v.y;
    }
#pragma unroll
    for (int off = 16; off; off >>= 1) {
        p0 += __shfl_xor_sync(0xffffffffu, p0, off);
        p1 += __shfl_xor_sync(0xffffffffu, p1, off);
    }
    if (lane == 0) {
        float dd = dis[node];
        float d2 = dd * dd;
        float2 sv = *(const float2*)(vin + (size_t)node * 2);
        float r0 = p0 + d2 * sv.x + g_s[sidx][0];
        float r1 = p1 + d2 * sv.y + g_s[sidx][1];
        if (LAST) {
            outp[(size_t)node * 2]     = 1.f / (1.f + expf(-r0));
            outp[(size_t)node * 2 + 1] = 1.f / (1.f + expf(-r1));
        } else {
            vout[(size_t)node * 2]     = r0;
            vout[(size_t)node * 2 + 1] = r1;
        }
    }
}

// ---------------------------------------------------------------------------
// Launch — R15 schedule + fused z epilogue (no zmma kernel)
// ---------------------------------------------------------------------------
extern "C" void kernel_launch(void* const* d_in, const int* in_sizes, int n_in,
                              void* d_out, int out_size)
{
    const float* x = (const float*)d_in[0];
    const void* ei = d_in[1];
    const float* W1  = (const float*)d_in[2];
    const float* b1  = (const float*)d_in[3];
    const float* W2  = (const float*)d_in[4];
    const float* b2  = (const float*)d_in[5];
    const float* Wc  = (const float*)d_in[6];
    const float* bc  = (const float*)d_in[7];
    const float* We1 = (const float*)d_in[8];
    const float* be1 = (const float*)d_in[9];
    const float* We2 = (const float*)d_in[10];
    const float* be2 = (const float*)d_in[11];
    const float* We3 = (const float*)d_in[12];
    const float* be3 = (const float*)d_in[13];
    const float* We4 = (const float*)d_in[14];
    const float* be4 = (const float*)d_in[15];
    const float* Wt  = (const float*)d_in[16];
    const float* bt  = (const float*)d_in[17];
    float* out = (float*)d_out;

    const int N = in_sizes[0] / 128;
    const int E = in_sizes[1] / 2;
    const int nscan = (N + SCAN_BS - 1) / SCAN_BS;

    float *dis, *z, *y, *y2;
    __nv_bfloat16 *whi, *wlo, *pDhi, *pDlo;
    cudaGetSymbolAddress((void**)&dis, g_dis);
    cudaGetSymbolAddress((void**)&z, g_z);
    cudaGetSymbolAddress((void**)&y, g_y);
    cudaGetSymbolAddress((void**)&y2, g_y2);
    cudaGetSymbolAddress((void**)&whi, g_whi);
    cudaGetSymbolAddress((void**)&wlo, g_wlo);
    cudaGetSymbolAddress((void**)&pDhi, g_pDhi);
    cudaGetSymbolAddress((void**)&pDlo, g_pDlo);

    cudaFuncSetAttribute(gemm_z_kernel, cudaFuncAttributeMaxDynamicSharedMemorySize, GEMM_SMEM);

    // One-time side stream + events
    static cudaStream_t s2 = nullptr;
    static cudaEvent_t evS = nullptr, evW = nullptr, evA = nullptr, evB = nullptr;
    if (!s2) {
        cudaStreamCreateWithFlags(&s2, cudaStreamNonBlocking);
        cudaEventCreateWithFlags(&evS, cudaEventDisableTiming);
        cudaEventCreateWithFlags(&evW, cudaEventDisableTiming);
        cudaEventCreateWithFlags(&evA, cudaEventDisableTiming);
        cudaEventCreateWithFlags(&evB, cudaEventDisableTiming);
    }

    // --- fork: weight prep on s2 ---
    cudaEventRecord(evS, 0);
    cudaStreamWaitEvent(s2, evS, 0);
    conv_w_kernel<<<128, 256, 0, s2>>>(W1);
    gwc_kernel<<<16, 256, 0, s2>>>(W2, Wc, b2, bc);
    enc_chain_kernel<<<1, 256, 0, s2>>>(We1, We2, We3, We4, Wt, be1, be2, be3, be4, bt);
    cudaEventRecord(evW, s2);

    // --- edge preprocessing + z zero on default stream ---
    zero_z_kernel<<<(N * 16 + 255) / 256, 256>>>(N);
    init_kernel<<<(N + 255) / 256, 256>>>(ei, N);
    count_kernel<<<(E + 255) / 256, 256>>>(ei, E);
    scan_blocks_kernel<<<nscan, SCAN_BS>>>(N);
    scan_tops_kernel<<<1, 512>>>(nscan);
    scan_add_fin_kernel<<<nscan, SCAN_BS>>>(N, E);
    fill_csr_kernel<<<(E + 255) / 256, 256>>>(ei, E);

    const int AGG_BLOCKS = (N + 7) / 8;
    dim3 gw((N + 127) / 128, 2);

    // aggx needs q — join weight prep
    cudaStreamWaitEvent(0, evW, 0);
    aggx_xq_kernel<<<AGG_BLOCKS, 256>>>(x, pDhi, pDlo, y, dis, N);
    cudaEventRecord(evA, 0);

    // --- encoder chain on s2, overlapped with classification chain ---
    cudaStreamWaitEvent(s2, evA, 0);
    prop2_kernel<false><<<AGG_BLOCKS, 256, 0, s2>>>(y, y2, dis, nullptr, 0, N);
    prop2_kernel<false><<<AGG_BLOCKS, 256, 0, s2>>>(y2, y, dis, nullptr, 1, N);
    prop2_kernel<false><<<AGG_BLOCKS, 256, 0, s2>>>(y, y2, dis, nullptr, 2, N);
    prop2_kernel<true><<<AGG_BLOCKS, 256, 0, s2>>>(y2, nullptr, dis, out + (size_t)N * 16, 3, N);
    cudaEventRecord(evB, s2);

    // --- classification chain on default stream ---
    gemm_z_kernel<<<gw, 256, GEMM_SMEM>>>(pDhi, pDlo, whi, wlo, b1, z, N, 128);
    prop16_kernel<<<AGG_BLOCKS, 256>>>(z, out, dis, N);

    // join encoder branch
    cudaStreamWaitEvent(0, evB, 0);
}